// round 16
// baseline (speedup 1.0000x reference)
#include <cuda_runtime.h>
#include <cuda_bf16.h>

// Output depends only on per-graph means of ORIGINAL node features + tiny MLP.
// (GraphConv layers in the reference are dead code — faithful DGL HeteroGraphConv
// bug: port1/net1/net2 are computed, deleted, never used.)
//
// Base = R12 (best: 18.9us), block split reverted to iteration-balanced
// 32/128/48. Single change: 2 nodes/thread via vectorized loads in the same
// grid-stride loop -> iterations halve (12->6) while the per-iteration
// dependent chain (ballot/shfl/tree/atomic) is unchanged.

#define NGRAPHS 64
#define TPB 256

__device__ float g_sum[NGRAPHS * 4];   // [b*4+col], col {comp:0, port:1,2, net:3}
__device__ float g_cnt[NGRAPHS * 3];   // [type*64+b]

// Warp-cooperative segmented accumulation, 2 nodes/thread.
// gids sorted; warp covers 64 contiguous nodes -> fast path almost always.
template <int COLS>
__device__ __forceinline__ void accum_type(
    const float* __restrict__ x, const int* __restrict__ gid, int n,
    int blk0, int nblocks, float* s_sum, float* s_cnt)
{
    const int tid = threadIdx.x;
    const int stride = nblocks * TPB * 2;
    for (int base = blk0 * TPB * 2; base < n; base += stride) {
        const int i = base + tid * 2;
        const bool full = (i + 1 < n);

        int ga = 0, gb = 0;
        float ls[COLS];
#pragma unroll
        for (int c = 0; c < COLS; c++) ls[c] = 0.0f;

        if (full) {
            const int2 gv = *reinterpret_cast<const int2*>(gid + i);
            ga = gv.x; gb = gv.y;
            if (COLS == 1) {
                const float2 xv = *reinterpret_cast<const float2*>(x + i);
                ls[0] = xv.x + xv.y;
            } else {
                const float4 a = *reinterpret_cast<const float4*>(x + i * 2);
                ls[0] = a.x + a.z;
                if (COLS > 1) ls[1] = a.y + a.w;
            }
        }

        const unsigned fm = __ballot_sync(0xffffffffu, full);
        const int g0 = __shfl_sync(0xffffffffu, ga, 0);
        const bool uni = __all_sync(0xffffffffu, (!full) || (ga == g0 && gb == g0));

        if (uni && fm) {
#pragma unroll
            for (int c = 0; c < COLS; c++) {
                float s = ls[c];
#pragma unroll
                for (int off = 16; off > 0; off >>= 1)
                    s += __shfl_xor_sync(0xffffffffu, s, off);
                if ((tid & 31) == 0) atomicAdd(&s_sum[g0 * COLS + c], s);
            }
            if ((tid & 31) == 0) atomicAdd(&s_cnt[g0], 2.0f * (float)__popc(fm));
            // odd-tail single node (at most one lane, last chunk of the type)
            if (!full && i < n) {
                const int g = gid[i];
#pragma unroll
                for (int c = 0; c < COLS; c++)
                    atomicAdd(&s_sum[g * COLS + c], x[i * COLS + c]);
                atomicAdd(&s_cnt[g], 1.0f);
            }
        } else {
            // segment boundary within the warp's 64 nodes (rare)
#pragma unroll
            for (int j = 0; j < 2; j++) {
                const int ii = i + j;
                if (ii < n) {
                    const int g = gid[ii];
#pragma unroll
                    for (int c = 0; c < COLS; c++)
                        atomicAdd(&s_sum[g * COLS + c], x[ii * COLS + c]);
                    atomicAdd(&s_cnt[g], 1.0f);
                }
            }
        }
    }
}

// Iteration-balanced split (~12 chunk-iterations per block at 512 nodes/iter -> ~6)
#define NB_COMP 32
#define NB_PORT 128
#define NB_NET  48
#define NB_TOTAL (NB_COMP + NB_PORT + NB_NET)   // 208

__global__ void accum_kernel(
    const float* __restrict__ h_comp, const int* __restrict__ gid_comp, int nc,
    const float* __restrict__ h_port, const int* __restrict__ gid_port, int np,
    const float* __restrict__ h_net,  const int* __restrict__ gid_net,  int nn)
{
    __shared__ float s_sum[NGRAPHS * 2];
    __shared__ float s_cnt[NGRAPHS];
    const int tid = threadIdx.x;
    if (tid < NGRAPHS * 2) s_sum[tid] = 0.0f;
    if (tid < NGRAPHS) s_cnt[tid] = 0.0f;
    __syncthreads();

    const int blk = blockIdx.x;
    int type, cols, sum_off;
    if (blk < NB_COMP) {
        accum_type<1>(h_comp, gid_comp, nc, blk, NB_COMP, s_sum, s_cnt);
        type = 0; cols = 1; sum_off = 0;
    } else if (blk < NB_COMP + NB_PORT) {
        accum_type<2>(h_port, gid_port, np, blk - NB_COMP, NB_PORT, s_sum, s_cnt);
        type = 1; cols = 2; sum_off = 1;
    } else {
        accum_type<1>(h_net, gid_net, nn, blk - NB_COMP - NB_PORT, NB_NET, s_sum, s_cnt);
        type = 2; cols = 1; sum_off = 3;
    }
    __syncthreads();

    if (tid < NGRAPHS * cols) {
        const int b = tid / cols, c = tid % cols;
        atomicAdd(&g_sum[b * 4 + sum_off + c], s_sum[tid]);
    }
    if (tid < NGRAPHS) {
        atomicAdd(&g_cnt[type * NGRAPHS + tid], s_cnt[tid]);
    }
}

// One block per graph, 256 threads = 8 k-chunks x 32 j-quads.
// Self-cleans the scratch for the next replay (reads barrier-protected).
__global__ void __launch_bounds__(TPB)
mlp_kernel(
    const float* __restrict__ Wc1, const float* __restrict__ bc1,
    const float* __restrict__ Wc2, const float* __restrict__ bc2,
    const float* __restrict__ Wc3, const float* __restrict__ bc3,
    float* __restrict__ out)
{
    __shared__ float sWc1[4 * 128];
    __shared__ float sWc3[128 * 10];
    __shared__ float sB[128 + 128 + 16];   // bc1 | bc2 | bc3
    __shared__ float part[8 * 128];
    __shared__ float tmp[8], hg[4], h1[128], h2[128];

    const int tid = threadIdx.x;
    const int b = blockIdx.x;
    const int jq = tid & 31;    // j-quad: columns jq*4..jq*4+3
    const int kc = tid >> 5;    // k-chunk 0..7 (16 k each)

    // ---- issue ALL Wc2 loads first: 16 independent float4s -> regs ----
    float4 w[16];
#pragma unroll
    for (int k = 0; k < 16; k++)
        w[k] = *reinterpret_cast<const float4*>(Wc2 + (kc * 16 + k) * 128 + jq * 4);

    // ---- under the same latency shadow: stage small weights + read scratch ----
    sWc1[tid] = Wc1[tid];
    sWc1[tid + 256] = Wc1[tid + 256];
#pragma unroll
    for (int r = 0; r < 5; r++) sWc3[r * 256 + tid] = Wc3[r * 256 + tid];
    sB[tid] = (tid < 128) ? bc1[tid] : bc2[tid - 128];
    if (tid < 10) sB[256 + tid] = bc3[tid];
    if (tid < 4) tmp[tid] = g_sum[b * 4 + tid];
    else if (tid < 7) tmp[tid] = g_cnt[(tid - 4) * NGRAPHS + b];
    __syncthreads();

    // self-clean scratch for the next call (reads complete past the barrier;
    // only this block touches graph b's entries)
    if (tid < 4) g_sum[b * 4 + tid] = 0.0f;
    else if (tid < 7) g_cnt[(tid - 4) * NGRAPHS + b] = 0.0f;

    if (tid < 4) {
        const int t = (tid == 0) ? 0 : (tid < 3 ? 1 : 2);
        hg[tid] = tmp[tid] / fmaxf(tmp[4 + t], 1.0f);
    }
    __syncthreads();

    // layer 1: [4] -> [128]
    if (tid < 128) {
        float a = sB[tid];
#pragma unroll
        for (int k = 0; k < 4; k++) a = fmaf(hg[k], sWc1[k * 128 + tid], a);
        h1[tid] = fmaxf(a, 0.0f);
    }
    __syncthreads();

    // layer 2: [128] -> [128] with register-resident Wc2 slice
    {
        float a0 = 0.f, a1 = 0.f, a2 = 0.f, a3 = 0.f;
#pragma unroll
        for (int k = 0; k < 16; k++) {
            const float s = h1[kc * 16 + k];
            a0 = fmaf(s, w[k].x, a0);
            a1 = fmaf(s, w[k].y, a1);
            a2 = fmaf(s, w[k].z, a2);
            a3 = fmaf(s, w[k].w, a3);
        }
        *reinterpret_cast<float4*>(part + kc * 128 + jq * 4) = make_float4(a0, a1, a2, a3);
    }
    __syncthreads();
    if (tid < 128) {
        float a = sB[128 + tid];
#pragma unroll
        for (int c = 0; c < 8; c++) a += part[c * 128 + tid];
        h2[tid] = fmaxf(a, 0.0f);
    }
    __syncthreads();

    // layer 3: [128] -> [10]; 16 j-lanes (10 real) x 16 k-chunks of 8
    {
        const int j = tid & 15;
        const int c = tid >> 4;        // 0..15
        if (j < 10) {
            const int k0 = c * 8;
            float acc = 0.f;
#pragma unroll
            for (int k = 0; k < 8; k++)
                acc = fmaf(h2[k0 + k], sWc3[(k0 + k) * 10 + j], acc);
            part[c * 16 + j] = acc;
        }
    }
    __syncthreads();
    if (tid < 10) {
        float c = sB[256 + tid];
#pragma unroll
        for (int cc = 0; cc < 16; cc++) c += part[cc * 16 + tid];
        out[b * 10 + tid] = c;
    }
}

extern "C" void kernel_launch(void* const* d_in, const int* in_sizes, int n_in,
                              void* d_out, int out_size)
{
    const float* h_comp   = (const float*)d_in[0];
    const float* h_port   = (const float*)d_in[1];
    const float* h_net    = (const float*)d_in[2];
    // d_in[3..6] edges, d_in[10..21] conv weights: dead code in reference
    const int*   gid_comp = (const int*)d_in[7];
    const int*   gid_port = (const int*)d_in[8];
    const int*   gid_net  = (const int*)d_in[9];
    const float* Wc1 = (const float*)d_in[22];
    const float* bc1 = (const float*)d_in[23];
    const float* Wc2 = (const float*)d_in[24];
    const float* bc2 = (const float*)d_in[25];
    const float* Wc3 = (const float*)d_in[26];
    const float* bc3 = (const float*)d_in[27];

    const int nc = in_sizes[0];
    const int np = in_sizes[1] / 2;
    const int nn = in_sizes[2];

    accum_kernel<<<NB_TOTAL, TPB>>>(h_comp, gid_comp, nc,
                                    h_port, gid_port, np,
                                    h_net,  gid_net,  nn);
    mlp_kernel<<<NGRAPHS, TPB>>>(Wc1, bc1, Wc2, bc2, Wc3, bc3, (float*)d_out);
}

// round 17
// speedup vs baseline: 1.4981x; 1.4981x over previous
#include <cuda_runtime.h>
#include <cuda_bf16.h>

// Output depends only on per-graph means of ORIGINAL node features + tiny MLP.
// (GraphConv layers in the reference are dead code — faithful DGL HeteroGraphConv
// bug: port1/net1/net2 are computed, deleted, never used.)
//
// Base = R11 champion (18.9us), byte-identical except NB_* doubled:
// 32/128/48 -> 64/256/96. Inner loop untouched (proven load-bearing);
// per-block grid-stride iterations halve 12.2 -> 6.1 uniformly.

#define NGRAPHS 64
#define TPB 256

__device__ float g_sum[NGRAPHS * 4];   // [b*4+col], col {comp:0, port:1,2, net:3}
__device__ float g_cnt[NGRAPHS * 3];   // [type*64+b]

__global__ void zero_kernel() {
    int i = threadIdx.x;
    if (i < NGRAPHS * 4) g_sum[i] = 0.0f;
    if (i < NGRAPHS * 3) g_cnt[i] = 0.0f;
}

// Warp-cooperative segmented accumulation (R1/R11 version, byte-identical).
template <int COLS>
__device__ __forceinline__ void accum_type(
    const float* __restrict__ x, const int* __restrict__ gid, int n,
    int blk0, int nblocks, float* s_sum, float* s_cnt)
{
    const int tid = threadIdx.x;
    const int stride = nblocks * blockDim.x;
    for (int base = blk0 * blockDim.x; base < n; base += stride) {
        const int i = base + tid;
        const bool valid = (i < n);
        int g = 0;
        float v[COLS];
#pragma unroll
        for (int c = 0; c < COLS; c++) v[c] = 0.0f;
        if (valid) {
            g = gid[i];
#pragma unroll
            for (int c = 0; c < COLS; c++) v[c] = x[i * COLS + c];
        }
        const unsigned vm = __ballot_sync(0xffffffffu, valid);
        const int g0 = __shfl_sync(0xffffffffu, g, 0);
        const bool uni = __all_sync(0xffffffffu, (!valid) || (g == g0));
        if (uni) {
            const float cnt = (float)__popc(vm);
#pragma unroll
            for (int c = 0; c < COLS; c++) {
                float s = v[c];
#pragma unroll
                for (int off = 16; off > 0; off >>= 1)
                    s += __shfl_xor_sync(0xffffffffu, s, off);
                if ((tid & 31) == 0 && vm) atomicAdd(&s_sum[g0 * COLS + c], s);
            }
            if ((tid & 31) == 0 && vm) atomicAdd(&s_cnt[g0], cnt);
        } else {
            if (valid) {
#pragma unroll
                for (int c = 0; c < COLS; c++) atomicAdd(&s_sum[g * COLS + c], v[c]);
                atomicAdd(&s_cnt[g], 1.0f);
            }
        }
    }
}

// 2x the R11 split: iteration count per block halves, loop body identical.
#define NB_COMP 64
#define NB_PORT 256
#define NB_NET  96
#define NB_TOTAL (NB_COMP + NB_PORT + NB_NET)   // 416

__global__ void accum_kernel(
    const float* __restrict__ h_comp, const int* __restrict__ gid_comp, int nc,
    const float* __restrict__ h_port, const int* __restrict__ gid_port, int np,
    const float* __restrict__ h_net,  const int* __restrict__ gid_net,  int nn)
{
    __shared__ float s_sum[NGRAPHS * 2];
    __shared__ float s_cnt[NGRAPHS];
    const int tid = threadIdx.x;
    if (tid < NGRAPHS * 2) s_sum[tid] = 0.0f;
    if (tid < NGRAPHS) s_cnt[tid] = 0.0f;
    __syncthreads();

    const int blk = blockIdx.x;
    int type, cols, sum_off;
    if (blk < NB_COMP) {
        accum_type<1>(h_comp, gid_comp, nc, blk, NB_COMP, s_sum, s_cnt);
        type = 0; cols = 1; sum_off = 0;
    } else if (blk < NB_COMP + NB_PORT) {
        accum_type<2>(h_port, gid_port, np, blk - NB_COMP, NB_PORT, s_sum, s_cnt);
        type = 1; cols = 2; sum_off = 1;
    } else {
        accum_type<1>(h_net, gid_net, nn, blk - NB_COMP - NB_PORT, NB_NET, s_sum, s_cnt);
        type = 2; cols = 1; sum_off = 3;
    }
    __syncthreads();

    if (tid < NGRAPHS * cols) {
        const int b = tid / cols, c = tid % cols;
        atomicAdd(&g_sum[b * 4 + sum_off + c], s_sum[tid]);
    }
    if (tid < NGRAPHS) {
        atomicAdd(&g_cnt[type * NGRAPHS + tid], s_cnt[tid]);
    }
}

// One block per graph, 256 threads = 8 k-chunks x 32 j-quads (R7/R11 version).
__global__ void __launch_bounds__(TPB)
mlp_kernel(
    const float* __restrict__ Wc1, const float* __restrict__ bc1,
    const float* __restrict__ Wc2, const float* __restrict__ bc2,
    const float* __restrict__ Wc3, const float* __restrict__ bc3,
    float* __restrict__ out)
{
    __shared__ float sWc1[4 * 128];
    __shared__ float sWc3[128 * 10];
    __shared__ float sB[128 + 128 + 16];   // bc1 | bc2 | bc3
    __shared__ float part[8 * 128];
    __shared__ float tmp[8], hg[4], h1[128], h2[128];

    const int tid = threadIdx.x;
    const int b = blockIdx.x;
    const int jq = tid & 31;    // j-quad: columns jq*4..jq*4+3
    const int kc = tid >> 5;    // k-chunk 0..7 (16 k each)

    // ---- issue ALL Wc2 loads first: 16 independent float4s -> regs ----
    float4 w[16];
#pragma unroll
    for (int k = 0; k < 16; k++)
        w[k] = *reinterpret_cast<const float4*>(Wc2 + (kc * 16 + k) * 128 + jq * 4);

    // ---- under the same latency shadow: stage small weights + read scratch ----
    sWc1[tid] = Wc1[tid];
    sWc1[tid + 256] = Wc1[tid + 256];
#pragma unroll
    for (int r = 0; r < 5; r++) sWc3[r * 256 + tid] = Wc3[r * 256 + tid];
    sB[tid] = (tid < 128) ? bc1[tid] : bc2[tid - 128];
    if (tid < 10) sB[256 + tid] = bc3[tid];
    if (tid < 4) tmp[tid] = g_sum[b * 4 + tid];
    else if (tid < 7) tmp[tid] = g_cnt[(tid - 4) * NGRAPHS + b];
    __syncthreads();

    if (tid < 4) {
        const int t = (tid == 0) ? 0 : (tid < 3 ? 1 : 2);
        hg[tid] = tmp[tid] / fmaxf(tmp[4 + t], 1.0f);
    }
    __syncthreads();

    // layer 1: [4] -> [128]
    if (tid < 128) {
        float a = sB[tid];
#pragma unroll
        for (int k = 0; k < 4; k++) a = fmaf(hg[k], sWc1[k * 128 + tid], a);
        h1[tid] = fmaxf(a, 0.0f);
    }
    __syncthreads();

    // layer 2: [128] -> [128] with register-resident Wc2 slice
    {
        float a0 = 0.f, a1 = 0.f, a2 = 0.f, a3 = 0.f;
#pragma unroll
        for (int k = 0; k < 16; k++) {
            const float s = h1[kc * 16 + k];
            a0 = fmaf(s, w[k].x, a0);
            a1 = fmaf(s, w[k].y, a1);
            a2 = fmaf(s, w[k].z, a2);
            a3 = fmaf(s, w[k].w, a3);
        }
        *reinterpret_cast<float4*>(part + kc * 128 + jq * 4) = make_float4(a0, a1, a2, a3);
    }
    __syncthreads();
    if (tid < 128) {
        float a = sB[128 + tid];
#pragma unroll
        for (int c = 0; c < 8; c++) a += part[c * 128 + tid];
        h2[tid] = fmaxf(a, 0.0f);
    }
    __syncthreads();

    // layer 3: [128] -> [10]; 16 j-lanes (10 real) x 16 k-chunks of 8
    {
        const int j = tid & 15;
        const int c = tid >> 4;        // 0..15
        if (j < 10) {
            const int k0 = c * 8;
            float acc = 0.f;
#pragma unroll
            for (int k = 0; k < 8; k++)
                acc = fmaf(h2[k0 + k], sWc3[(k0 + k) * 10 + j], acc);
            part[c * 16 + j] = acc;
        }
    }
    __syncthreads();
    if (tid < 10) {
        float c = sB[256 + tid];
#pragma unroll
        for (int cc = 0; cc < 16; cc++) c += part[cc * 16 + tid];
        out[b * 10 + tid] = c;
    }
}

extern "C" void kernel_launch(void* const* d_in, const int* in_sizes, int n_in,
                              void* d_out, int out_size)
{
    const float* h_comp   = (const float*)d_in[0];
    const float* h_port   = (const float*)d_in[1];
    const float* h_net    = (const float*)d_in[2];
    // d_in[3..6] edges, d_in[10..21] conv weights: dead code in reference
    const int*   gid_comp = (const int*)d_in[7];
    const int*   gid_port = (const int*)d_in[8];
    const int*   gid_net  = (const int*)d_in[9];
    const float* Wc1 = (const float*)d_in[22];
    const float* bc1 = (const float*)d_in[23];
    const float* Wc2 = (const float*)d_in[24];
    const float* bc2 = (const float*)d_in[25];
    const float* Wc3 = (const float*)d_in[26];
    const float* bc3 = (const float*)d_in[27];

    const int nc = in_sizes[0];
    const int np = in_sizes[1] / 2;
    const int nn = in_sizes[2];

    zero_kernel<<<1, 256>>>();
    accum_kernel<<<NB_TOTAL, TPB>>>(h_comp, gid_comp, nc,
                                    h_port, gid_port, np,
                                    h_net,  gid_net,  nn);
    mlp_kernel<<<NGRAPHS, TPB>>>(Wc1, bc1, Wc2, bc2, Wc3, bc3, (float*)d_out);
}